// round 5
// baseline (speedup 1.0000x reference)
#include <cuda_runtime.h>
#include <math.h>

#define EPS 1e-6f
#define TB 16

// Plane (n, d): n.x + d = 0 through v0; t = 9 floats in shared.
__device__ __forceinline__ float4 plane_of(const float* t) {
    float v0x = t[0], v0y = t[1], v0z = t[2];
    float e1x = t[3] - v0x, e1y = t[4] - v0y, e1z = t[5] - v0z;
    float e2x = t[6] - v0x, e2y = t[7] - v0y, e2z = t[8] - v0z;
    float nx = e1y * e2z - e1z * e2y;
    float ny = e1z * e2x - e1x * e2z;
    float nz = e1x * e2y - e1y * e2x;
    float d = -(nx * v0x + ny * v0y + nz * v0z);
    return make_float4(nx, ny, nz, d);
}

// Interval of the intersection line covered by one triangle, built from
// sign predicates (p_k = d_k>0, n_k = d_k<0) and snapped distances.
// valid_k = !(pi&pj | ni&nj) & (pi|ni|pj|nj)  ==  (di*dj<=0) & !(di==0&dj==0)
// (equivalent for snapped |d|>=EPS: no underflow in di*dj possible).
// valid => di != dj, so the divide needs no guard.
__device__ __forceinline__ void interval3(const float p[3], const float d[3],
                                          const bool pp[3], const bool nn[3],
                                          float& tmin, float& tmax) {
    tmin = INFINITY;
    tmax = -INFINITY;
#pragma unroll
    for (int k = 0; k < 3; k++) {
        const int kn = (k == 2) ? 0 : k + 1;
        bool valid = !((pp[k] & pp[kn]) | (nn[k] & nn[kn])) &
                     (pp[k] | nn[k] | pp[kn] | nn[kn]);
        float t = p[k] + (p[kn] - p[k]) * __fdividef(d[k], d[k] - d[kn]);
        if (valid) {
            tmin = fminf(tmin, t);
            tmax = fmaxf(tmax, t);
        }
    }
}

__global__ void pair_kernel(const float* __restrict__ T,
                            float* __restrict__ out, int N) {
    // Linear block index -> upper-triangular tile (ti <= tj).
    const int k = blockIdx.x;
    int tj = (int)((sqrtf(8.0f * (float)k + 1.0f) - 1.0f) * 0.5f);
    while ((tj + 1) * (tj + 2) / 2 <= k) tj++;
    while (tj * (tj + 1) / 2 > k) tj--;
    const int ti = k - tj * (tj + 1) / 2;

    __shared__ float trR[TB][9];
    __shared__ float trC[TB][9];
    __shared__ float4 nR[TB], nC[TB];
    __shared__ float res[TB][TB + 1];

    const int tx = threadIdx.x, ty = threadIdx.y;
    const int tid = ty * TB + tx;
    const int i0 = ti * TB, j0 = tj * TB;

    for (int q = tid; q < TB * 9; q += TB * TB) {
        int r = q / 9, c = q % 9;
        int gi = i0 + r, gj = j0 + r;
        trR[r][c] = (gi < N) ? T[(size_t)gi * 9 + c] : 0.0f;
        trC[r][c] = (gj < N) ? T[(size_t)gj * 9 + c] : 0.0f;
    }
    __syncthreads();
    if (tid < TB) {
        nR[tid] = plane_of(trR[tid]);
    } else if (tid < 2 * TB) {
        nC[tid - TB] = plane_of(trC[tid - TB]);
    }
    __syncthreads();

    const int i = i0 + ty;
    const int j = j0 + tx;

    const float* A = trR[ty];
    const float* B = trC[tx];
    const float4 na = nR[ty];
    const float4 nb = nC[tx];

    // Signed distances with EPS snap, plus sign predicates.
    float dv[3], du[3];
    bool pv_[3], nv_[3], pu_[3], nu_[3];
#pragma unroll
    for (int v = 0; v < 3; v++) {
        float dd = A[3 * v] * nb.x + A[3 * v + 1] * nb.y +
                   A[3 * v + 2] * nb.z + nb.w;
        dd = (fabsf(dd) < EPS) ? 0.0f : dd;
        dv[v] = dd;
        pv_[v] = dd > 0.0f;
        nv_[v] = dd < 0.0f;
        float ee = B[3 * v] * na.x + B[3 * v + 1] * na.y +
                   B[3 * v + 2] * na.z + na.w;
        ee = (fabsf(ee) < EPS) ? 0.0f : ee;
        du[v] = ee;
        pu_[v] = ee > 0.0f;
        nu_[v] = ee < 0.0f;
    }

    bool ssv = (pv_[0] & pv_[1] & pv_[2]) | (nv_[0] & nv_[1] & nv_[2]);
    bool ssu = (pu_[0] & pu_[1] & pu_[2]) | (nu_[0] & nu_[1] & nu_[2]);

    // Dominant axis of plane-plane line direction (first-max argmax).
    float Dx = na.y * nb.z - na.z * nb.y;
    float Dy = na.z * nb.x - na.x * nb.z;
    float Dz = na.x * nb.y - na.y * nb.x;
    int ax = 0;
    float m = fabsf(Dx);
    if (fabsf(Dy) > m) { ax = 1; m = fabsf(Dy); }
    if (fabsf(Dz) > m) { ax = 2; }

    float pv[3], pu[3];
#pragma unroll
    for (int v = 0; v < 3; v++) {
        pv[v] = A[3 * v + ax];
        pu[v] = B[3 * v + ax];
    }

    float t0v, t1v, t0u, t1u;
    interval3(pv, dv, pv_, nv_, t0v, t1v);
    interval3(pu, du, pu_, nu_, t0u, t1u);
    bool overlap = fmaxf(t0v, t0u) <= fminf(t1v, t1u);

    res[ty][tx] = (!ssv & !ssu & overlap) ? 1.0f : 0.0f;
    __syncthreads();

    // Upper (and diagonal) tile: coalesced row writes.
    if (i < N && j < N) {
        float val;
        if (ti == tj) {
            val = (tx > ty) ? res[ty][tx] : ((tx == ty) ? 1.0f : res[tx][ty]);
        } else {
            val = res[ty][tx];
        }
        out[(size_t)i * N + j] = val;
    }
    // Mirror tile for strictly-off-diagonal blocks (also coalesced).
    if (ti != tj) {
        int jj = j0 + ty, ii = i0 + tx;
        if (jj < N && ii < N) out[(size_t)jj * N + ii] = res[tx][ty];
    }
}

extern "C" void kernel_launch(void* const* d_in, const int* in_sizes, int n_in,
                              void* d_out, int out_size) {
    const float* T = (const float*)d_in[0];
    float* out = (float*)d_out;
    int N = in_sizes[0] / 9;

    int nt = (N + TB - 1) / TB;
    int nblk = nt * (nt + 1) / 2;
    pair_kernel<<<nblk, dim3(TB, TB)>>>(T, out, N);
}